// round 1
// baseline (speedup 1.0000x reference)
#include <cuda_runtime.h>
#include <math.h>

// ---------------- problem constants (fixed by setup_inputs) ----------------
#define KS    11          // kernel_size
#define HI    384         // input H (=W)
#define HO    512         // target H (=W)
#define HOUT  (HO - KS + 1)   // 502 valid conv outputs
#define TILE  32
#define PATCH (TILE + KS - 1) // 42
#define NTILES ((HOUT + TILE - 1) / TILE) // 16

// ---------------- device globals (no cudaMalloc allowed) ----------------
__device__ float  g_gauss[KS];   // normalized 1D gaussian (float32 of double-normalized)
__device__ int    g_idx0[HO];    // bilinear lower index per output coord
__device__ float  g_wgt[HO];     // bilinear weight per output coord
__device__ double g_accum;       // global ssim-map sum

// ---------------- setup: tables + accumulator zero ----------------
__global__ void ssim_setup_kernel() {
    int t = threadIdx.x;
    if (t < HO) {
        // align_corners=True: pos = o * (HI-1)/(HO-1), computed in double like numpy
        double pos = (double)t * (double)(HI - 1) / (double)(HO - 1);
        int i0 = (int)floor(pos);
        g_idx0[t] = i0;
        g_wgt[t]  = (float)(pos - (double)i0);
    }
    if (t == 0) {
        double g[KS], s = 0.0;
        const double sigma = 1.5;
        for (int i = 0; i < KS; i++) {
            double x = (double)i - (double)(KS / 2);
            g[i] = exp(-(x * x) / (2.0 * sigma * sigma));
            s += g[i];
        }
        for (int i = 0; i < KS; i++) g_gauss[i] = (float)(g[i] / s);
        g_accum = 0.0;
    }
}

// ---------------- main fused kernel ----------------
// One block = one 32x32 tile of the 502x502 ssim map for one (b,c) image.
// Fuses: bilinear resize (img1), 5 separable gaussian convs, SSIM map, reduction.
__global__ void __launch_bounds__(256)
ssim_tile_kernel(const float* __restrict__ input,   // [n_img, 384, 384]
                 const float* __restrict__ target)  // [n_img, 512, 512]
{
    const int img = blockIdx.z;
    const int ty0 = blockIdx.y * TILE;
    const int tx0 = blockIdx.x * TILE;

    __shared__ float s1[PATCH][PATCH + 2];   // resized input patch
    __shared__ float s2[PATCH][PATCH + 2];   // target patch
    __shared__ float hbuf[5][PATCH][TILE + 1]; // horizontal conv of {p1,p2,p1^2,p2^2,p1p2}
    __shared__ float gsh[KS];
    __shared__ int   ix0s[PATCH];
    __shared__ float wxs[PATCH];
    __shared__ float redbuf[8];

    const int tid = threadIdx.x;

    if (tid < KS) gsh[tid] = g_gauss[tid];
    if (tid < PATCH) {
        int gx = min(tx0 + tid, HO - 1);
        ix0s[tid] = g_idx0[gx];
        wxs[tid]  = g_wgt[gx];
    }
    __syncthreads();

    const float* inp = input  + (size_t)img * (HI * HI);
    const float* tgt = target + (size_t)img * (HO * HO);

    // ---- load patches: target direct, img1 via bilinear on the fly ----
    for (int e = tid; e < PATCH * PATCH; e += 256) {
        int r = e / PATCH;
        int c = e - r * PATCH;
        int gy = min(ty0 + r, HO - 1);
        int gx = min(tx0 + c, HO - 1);

        s2[r][c] = tgt[gy * HO + gx];

        int   iy0 = g_idx0[gy];
        float wy  = g_wgt[gy];
        int   iy1 = min(iy0 + 1, HI - 1);
        int   ix0 = ix0s[c];
        float wx  = wxs[c];
        int   ix1 = min(ix0 + 1, HI - 1);

        float a = inp[iy0 * HI + ix0];
        float b = inp[iy0 * HI + ix1];
        float cc = inp[iy1 * HI + ix0];
        float d  = inp[iy1 * HI + ix1];
        float top = a * (1.0f - wx) + b * wx;
        float bot = cc * (1.0f - wx) + d * wx;
        s1[r][c] = top * (1.0f - wy) + bot * wy;
    }
    __syncthreads();

    // ---- horizontal separable pass (products formed on the fly) ----
    for (int e = tid; e < PATCH * TILE; e += 256) {
        int r = e >> 5;        // /32
        int c = e & 31;
        float a1 = 0.f, a2 = 0.f, a11 = 0.f, a22 = 0.f, a12 = 0.f;
        #pragma unroll
        for (int k = 0; k < KS; k++) {
            float g  = gsh[k];
            float p1 = s1[r][c + k];
            float p2 = s2[r][c + k];
            a1  += g * p1;
            a2  += g * p2;
            a11 += g * (p1 * p1);
            a22 += g * (p2 * p2);
            a12 += g * (p1 * p2);
        }
        hbuf[0][r][c] = a1;
        hbuf[1][r][c] = a2;
        hbuf[2][r][c] = a11;
        hbuf[3][r][c] = a22;
        hbuf[4][r][c] = a12;
    }
    __syncthreads();

    // ---- vertical pass + SSIM map + local accumulation ----
    const float C1 = 1e-4f;   // (0.01*1)^2
    const float C2 = 9e-4f;   // (0.03*1)^2
    float lsum = 0.f;

    for (int e = tid; e < TILE * TILE; e += 256) {
        int ly = e >> 5;
        int lx = e & 31;
        int gy = ty0 + ly;
        int gx = tx0 + lx;
        if (gy < HOUT && gx < HOUT) {
            float mu1 = 0.f, mu2 = 0.f, x11 = 0.f, x22 = 0.f, x12 = 0.f;
            #pragma unroll
            for (int k = 0; k < KS; k++) {
                float g = gsh[k];
                mu1 += g * hbuf[0][ly + k][lx];
                mu2 += g * hbuf[1][ly + k][lx];
                x11 += g * hbuf[2][ly + k][lx];
                x22 += g * hbuf[3][ly + k][lx];
                x12 += g * hbuf[4][ly + k][lx];
            }
            float mu1sq = mu1 * mu1;
            float mu2sq = mu2 * mu2;
            float mu12  = mu1 * mu2;
            float sig1  = x11 - mu1sq;
            float sig2  = x22 - mu2sq;
            float sig12 = x12 - mu12;
            float v1 = 2.0f * sig12 + C2;
            float v2 = sig1 + sig2 + C2;
            float num = (2.0f * mu12 + C1) * v1;
            float den = (mu1sq + mu2sq + C1) * v2;
            lsum += num / den;
        }
    }

    // ---- block reduction (warp shuffle + smem), then one double atomic ----
    #pragma unroll
    for (int off = 16; off > 0; off >>= 1)
        lsum += __shfl_down_sync(0xFFFFFFFFu, lsum, off);
    int lane = tid & 31;
    int wid  = tid >> 5;
    if (lane == 0) redbuf[wid] = lsum;
    __syncthreads();
    if (wid == 0) {
        float v = (lane < 8) ? redbuf[lane] : 0.f;
        #pragma unroll
        for (int off = 4; off > 0; off >>= 1)
            v += __shfl_down_sync(0xFFFFFFFFu, v, off);
        if (lane == 0) atomicAdd(&g_accum, (double)v);
    }
}

// ---------------- finalize: mean -> 1-mean -> clip ----------------
__global__ void ssim_finalize_kernel(float* __restrict__ out, long long count) {
    double mean = g_accum / (double)count;
    double loss = 1.0 - mean;
    if (loss < 0.0) loss = 0.0;
    if (loss > 1.0) loss = 1.0;
    out[0] = (float)loss;
}

// ---------------- launch ----------------
extern "C" void kernel_launch(void* const* d_in, const int* in_sizes, int n_in,
                              void* d_out, int out_size) {
    const float* input  = (const float*)d_in[0];
    const float* target = (const float*)d_in[1];
    int sz0 = in_sizes[0], sz1 = in_sizes[1];
    // input is the smaller tensor (384^2 vs 512^2 per image)
    if (sz0 > sz1) {
        const float* t = input; input = target; target = t;
        int ts = sz0; sz0 = sz1; sz1 = ts;
    }
    int n_img = sz0 / (HI * HI);   // B*C = 96

    ssim_setup_kernel<<<1, 512>>>();

    dim3 grid(NTILES, NTILES, n_img);
    ssim_tile_kernel<<<grid, 256>>>(input, target);

    long long count = (long long)n_img * HOUT * HOUT;
    ssim_finalize_kernel<<<1, 1>>>((float*)d_out, count);
}

// round 2
// speedup vs baseline: 1.4153x; 1.4153x over previous
#include <cuda_runtime.h>
#include <math.h>

// ---------------- problem constants ----------------
#define KS    11
#define HI    384
#define HO    512
#define HOUT  (HO - KS + 1)     // 502
#define TILE  32
#define PATCH (TILE + KS - 1)   // 42
#define NTILES ((HOUT + TILE - 1) / TILE) // 16

typedef unsigned long long ull;

// Gaussian weights (sigma=1.5, ks=11), double-normalized then rounded to f32.
// Hand-computed to ~1e-8 relative accuracy; sum == 1.0.
#define GW0  0.0010283801f
#define GW1  0.0075987582f
#define GW2  0.0360007722f
#define GW3  0.1093606884f
#define GW4  0.2130055383f
#define GW5  0.2660117256f
__device__ __constant__ float c_unused; // keep compiler happy about constants usage

__device__ double g_accum;

// ---------------- f32x2 packed helpers ----------------
__device__ __forceinline__ ull pk2(float lo, float hi) {
    ull r;
    asm("mov.b64 %0, {%1, %2};" : "=l"(r) : "f"(lo), "f"(hi));
    return r;
}
__device__ __forceinline__ void up2(ull v, float& lo, float& hi) {
    asm("mov.b64 {%0, %1}, %2;" : "=f"(lo), "=f"(hi) : "l"(v));
}
__device__ __forceinline__ ull pfma(ull a, ull b, ull c) {
    ull d;
    asm("fma.rn.f32x2 %0, %1, %2, %3;" : "=l"(d) : "l"(a), "l"(b), "l"(c));
    return d;
}
__device__ __forceinline__ ull pmul(ull a, ull b) {
    ull d;
    asm("mul.rn.f32x2 %0, %1, %2;" : "=l"(d) : "l"(a), "l"(b));
    return d;
}

__global__ void ssim_zero_kernel() { g_accum = 0.0; }

// ---------------- main fused kernel ----------------
__global__ void __launch_bounds__(256)
ssim_tile_kernel(const float* __restrict__ input,   // [96, 384, 384]
                 const float* __restrict__ target)  // [96, 512, 512]
{
    const int img = blockIdx.z;
    const int ty0 = blockIdx.y * TILE;
    const int tx0 = blockIdx.x * TILE;
    const int tid = threadIdx.x;

    // interleaved (img1, img2) patch; padded stride 46 for STS/LDS behavior
    __shared__ ull   s12[PATCH][PATCH + 4];      // 42*46*8 = 15456 B
    __shared__ ull   hmu[PATCH][TILE + 1];       // (mu1h, mu2h)   11088 B
    __shared__ ull   hsq[PATCH][TILE + 1];       // (x11h, x22h)   11088 B
    __shared__ float hx12[PATCH][TILE + 1];      // x12h            5544 B
    __shared__ float redbuf[8];

    const float GW[KS] = {GW0, GW1, GW2, GW3, GW4, GW5, GW4, GW3, GW2, GW1, GW0};
    ull CS[KS];
    #pragma unroll
    for (int k = 0; k < KS; k++) CS[k] = pk2(GW[k], GW[k]);

    const float* inp = input  + (size_t)img * (HI * HI);
    const float* tgt = target + (size_t)img * (HO * HO);

    // ---- load: target direct, img1 bilinear (exact integer index math) ----
    for (int e = tid; e < PATCH * PATCH; e += 256) {
        int r = e / PATCH;
        int c = e - r * PATCH;
        int gy = min(ty0 + r, HO - 1);
        int gx = min(tx0 + c, HO - 1);

        float t2 = tgt[gy * HO + gx];

        int py = gy * (HI - 1);             // pos_y * 511
        int iy0 = py / (HO - 1);
        float wy = (float)(py - iy0 * (HO - 1)) * (1.0f / (float)(HO - 1));
        int iy1 = min(iy0 + 1, HI - 1);
        int px = gx * (HI - 1);
        int ix0 = px / (HO - 1);
        float wx = (float)(px - ix0 * (HO - 1)) * (1.0f / (float)(HO - 1));
        int ix1 = min(ix0 + 1, HI - 1);

        float a  = inp[iy0 * HI + ix0];
        float b  = inp[iy0 * HI + ix1];
        float cc = inp[iy1 * HI + ix0];
        float d  = inp[iy1 * HI + ix1];
        float top = a  * (1.0f - wx) + b * wx;
        float bot = cc * (1.0f - wx) + d * wx;
        float v1  = top * (1.0f - wy) + bot * wy;

        s12[r][c] = pk2(v1, t2);
    }
    __syncthreads();

    // ---- horizontal pass: sliding window, 4 output cols per task ----
    // task e: row r = e>>3 (0..41), col group c0 = (e&7)*4
    for (int e = tid; e < PATCH * 8; e += 256) {
        int r  = e >> 3;
        int c0 = (e & 7) << 2;

        ull aM0 = 0, aM1 = 0, aM2 = 0, aM3 = 0;
        ull aS0 = 0, aS1 = 0, aS2 = 0, aS3 = 0;
        float aX0 = 0.f, aX1 = 0.f, aX2 = 0.f, aX3 = 0.f;

        #pragma unroll
        for (int j = 0; j < TILE / 8 * 0 + 14; j++) {   // j = 0..13
            ull pk = s12[r][c0 + j];
            float p1, p2;
            up2(pk, p1, p2);
            ull sq = pmul(pk, pk);           // (p1*p1, p2*p2)
            float p12 = p1 * p2;

            // output o gets coefficient GW[j-o] when 0 <= j-o <= 10
            #pragma unroll
            for (int o = 0; o < 4; o++) {
                int k = j - o;
                if (k >= 0 && k < KS) {
                    ull cs = CS[k];
                    float g = GW[k];
                    if (o == 0) { aM0 = pfma(pk, cs, aM0); aS0 = pfma(sq, cs, aS0); aX0 = fmaf(g, p12, aX0); }
                    if (o == 1) { aM1 = pfma(pk, cs, aM1); aS1 = pfma(sq, cs, aS1); aX1 = fmaf(g, p12, aX1); }
                    if (o == 2) { aM2 = pfma(pk, cs, aM2); aS2 = pfma(sq, cs, aS2); aX2 = fmaf(g, p12, aX2); }
                    if (o == 3) { aM3 = pfma(pk, cs, aM3); aS3 = pfma(sq, cs, aS3); aX3 = fmaf(g, p12, aX3); }
                }
            }
        }
        hmu[r][c0 + 0] = aM0; hmu[r][c0 + 1] = aM1; hmu[r][c0 + 2] = aM2; hmu[r][c0 + 3] = aM3;
        hsq[r][c0 + 0] = aS0; hsq[r][c0 + 1] = aS1; hsq[r][c0 + 2] = aS2; hsq[r][c0 + 3] = aS3;
        hx12[r][c0 + 0] = aX0; hx12[r][c0 + 1] = aX1; hx12[r][c0 + 2] = aX2; hx12[r][c0 + 3] = aX3;
    }
    __syncthreads();

    // ---- vertical pass + SSIM + reduction ----
    const int lx = tid & 31;
    const int o0 = (tid >> 5) << 2;      // 4 output rows per thread

    ull aM0 = 0, aM1 = 0, aM2 = 0, aM3 = 0;
    ull aS0 = 0, aS1 = 0, aS2 = 0, aS3 = 0;
    float aX0 = 0.f, aX1 = 0.f, aX2 = 0.f, aX3 = 0.f;

    #pragma unroll
    for (int rel = 0; rel < 14; rel++) {
        int rr = o0 + rel;
        ull vM = hmu[rr][lx];
        ull vS = hsq[rr][lx];
        float vX = hx12[rr][lx];

        #pragma unroll
        for (int o = 0; o < 4; o++) {
            int k = rel - o;
            if (k >= 0 && k < KS) {
                ull cs = CS[k];
                float g = GW[k];
                if (o == 0) { aM0 = pfma(vM, cs, aM0); aS0 = pfma(vS, cs, aS0); aX0 = fmaf(g, vX, aX0); }
                if (o == 1) { aM1 = pfma(vM, cs, aM1); aS1 = pfma(vS, cs, aS1); aX1 = fmaf(g, vX, aX1); }
                if (o == 2) { aM2 = pfma(vM, cs, aM2); aS2 = pfma(vS, cs, aS2); aX2 = fmaf(g, vX, aX2); }
                if (o == 3) { aM3 = pfma(vM, cs, aM3); aS3 = pfma(vS, cs, aS3); aX3 = fmaf(g, vX, aX3); }
            }
        }
    }

    const float C1 = 1e-4f;
    const float C2 = 9e-4f;
    float lsum = 0.f;
    const int gx = tx0 + lx;

    #pragma unroll
    for (int o = 0; o < 4; o++) {
        int gy = ty0 + o0 + o;
        if (gy < HOUT && gx < HOUT) {
            ull am = (o == 0) ? aM0 : (o == 1) ? aM1 : (o == 2) ? aM2 : aM3;
            ull as = (o == 0) ? aS0 : (o == 1) ? aS1 : (o == 2) ? aS2 : aS3;
            float ax = (o == 0) ? aX0 : (o == 1) ? aX1 : (o == 2) ? aX2 : aX3;
            float mu1, mu2, x11, x22;
            up2(am, mu1, mu2);
            up2(as, x11, x22);
            float mu1sq = mu1 * mu1;
            float mu2sq = mu2 * mu2;
            float mu12  = mu1 * mu2;
            float sig1  = x11 - mu1sq;
            float sig2  = x22 - mu2sq;
            float sig12 = ax  - mu12;
            float v1 = 2.0f * sig12 + C2;
            float v2 = sig1 + sig2 + C2;
            float num = (2.0f * mu12 + C1) * v1;
            float den = (mu1sq + mu2sq + C1) * v2;
            lsum += num / den;
        }
    }

    // block reduction
    #pragma unroll
    for (int off = 16; off > 0; off >>= 1)
        lsum += __shfl_down_sync(0xFFFFFFFFu, lsum, off);
    int lane = tid & 31;
    int wid  = tid >> 5;
    if (lane == 0) redbuf[wid] = lsum;
    __syncthreads();
    if (wid == 0) {
        float v = (lane < 8) ? redbuf[lane] : 0.f;
        #pragma unroll
        for (int off = 4; off > 0; off >>= 1)
            v += __shfl_down_sync(0xFFFFFFFFu, v, off);
        if (lane == 0) atomicAdd(&g_accum, (double)v);
    }
}

__global__ void ssim_finalize_kernel(float* __restrict__ out, long long count) {
    double mean = g_accum / (double)count;
    double loss = 1.0 - mean;
    if (loss < 0.0) loss = 0.0;
    if (loss > 1.0) loss = 1.0;
    out[0] = (float)loss;
}

extern "C" void kernel_launch(void* const* d_in, const int* in_sizes, int n_in,
                              void* d_out, int out_size) {
    const float* input  = (const float*)d_in[0];
    const float* target = (const float*)d_in[1];
    int sz0 = in_sizes[0], sz1 = in_sizes[1];
    if (sz0 > sz1) {
        const float* t = input; input = target; target = t;
        int ts = sz0; sz0 = sz1; sz1 = ts;
    }
    int n_img = sz0 / (HI * HI);   // 96

    ssim_zero_kernel<<<1, 1>>>();

    dim3 grid(NTILES, NTILES, n_img);
    ssim_tile_kernel<<<grid, 256>>>(input, target);

    long long count = (long long)n_img * HOUT * HOUT;
    ssim_finalize_kernel<<<1, 1>>>((float*)d_out, count);
}